// round 16
// baseline (speedup 1.0000x reference)
#include <cuda_runtime.h>
#include <cuda_fp16.h>
#include <cstdint>
#include <cstddef>

// Scratch: E = enc@W^T (2048x1024), D = dec@W^T + bias (512x1024)
__device__ float g_E[2048 * 1024];
__device__ float g_D[512 * 1024];

// fp16 copies of inputs: [enc | dec | W]
constexpr size_t ENC_N = 2048 * 512, DEC_N = 512 * 512, W_N = 1024 * 512;
__device__ __half g_H[ENC_N + DEC_N + W_N];

constexpr size_t ENC01_N = 512 * 512;        // enc rows 0..511 (b0,b1)

constexpr int KDIM = 512, NDIM = 1024;
constexpr int BM = 64, BN = 128;
constexpr int BK2 = 32;                      // half2 k-rows per tile (64 halves)
constexpr int NKT = KDIM / 64;               // 8 k-tiles
constexpr int STRA = 72, STRB = 136;         // conflict-free padded strides

__device__ __forceinline__ void mma_f16(float* c, const uint32_t* a, const uint32_t* b) {
    asm volatile(
        "mma.sync.aligned.m16n8k16.row.col.f32.f16.f16.f32 "
        "{%0,%1,%2,%3}, {%4,%5,%6,%7}, {%8,%9}, {%0,%1,%2,%3};\n"
        : "+f"(c[0]), "+f"(c[1]), "+f"(c[2]), "+f"(c[3])
        : "r"(a[0]), "r"(a[1]), "r"(a[2]), "r"(a[3]), "r"(b[0]), "r"(b[1]));
}

__device__ __forceinline__ uint32_t pack_h2(float x, float y) {
    __half2 h = __floats2half2_rn(x, y);
    return *reinterpret_cast<uint32_t*>(&h);
}

// ---------------------------------------------------------------------------
// cvtA: dec + W + enc rows 0..511 (everything gemmA needs). 512 blocks.
// cvtB: enc rows 512..2047. 384 blocks. Both 8 floats/thread.
// ---------------------------------------------------------------------------
__global__ void __launch_bounds__(256)
cvtA_f16(const float* __restrict__ enc, const float* __restrict__ dec,
         const float* __restrict__ W)
{
    const size_t j = ((size_t)blockIdx.x * 256 + threadIdx.x) * 8;
    const float* src;
    size_t off, dst;
    if (j < ENC01_N)              { src = enc; off = j;            dst = off; }
    else if (j < ENC01_N + DEC_N) { src = dec; off = j - ENC01_N;  dst = ENC_N + off; }
    else                          { src = W;   off = j - ENC01_N - DEC_N;
                                    dst = ENC_N + DEC_N + off; }
    float4 a = *(const float4*)(src + off);
    float4 b = *(const float4*)(src + off + 4);
    uint4 o;
    o.x = pack_h2(a.x, a.y); o.y = pack_h2(a.z, a.w);
    o.z = pack_h2(b.x, b.y); o.w = pack_h2(b.z, b.w);
    *(uint4*)(&g_H[dst]) = o;
}

__global__ void __launch_bounds__(256)
cvtB_f16(const float* __restrict__ enc)
{
    const size_t off = ENC01_N + ((size_t)blockIdx.x * 256 + threadIdx.x) * 8;
    float4 a = *(const float4*)(enc + off);
    float4 b = *(const float4*)(enc + off + 4);
    uint4 o;
    o.x = pack_h2(a.x, a.y); o.y = pack_h2(a.z, a.w);
    o.z = pack_h2(b.x, b.y); o.w = pack_h2(b.z, b.w);
    *(uint4*)(&g_H[off]) = o;
}

// ---------------------------------------------------------------------------
// fp16-input NT GEMM, low-latency tile: 64x128, 256 thr, 8 warps (2x4),
// warp tile 32x32, BK=64 halves (8 k-tiles). ~2-3 CTAs/SM.
// yidx = blockIdx.y + y0: 0..7 -> D row-tile (dec,+bias); 8..39 -> E row-tile.
// ---------------------------------------------------------------------------
__global__ void __launch_bounds__(256)
gemm_f16(const float* __restrict__ bias, float* __restrict__ E,
         float* __restrict__ D, int y0)
{
    __shared__ uint32_t As[BK2][STRA];
    __shared__ uint32_t Bs[BK2][STRB];

    const __half* encH = g_H;
    const __half* decH = g_H + ENC_N;
    const __half* WH   = g_H + ENC_N + DEC_N;

    const int tid  = threadIdx.x;
    const int col0 = blockIdx.x * BN;
    const int yidx = blockIdx.y + y0;
    const bool isE = (yidx >= 8);
    const int row0 = isE ? (yidx - 8) * BM : yidx * BM;
    const __half* A = isE ? encH : decH;
    float* C        = isE ? E : D;

    // A staging: 4 thr/row (64 rows), each 16 halves (2 uint4)
    const int arow = tid >> 2;
    const int k2q  = (tid & 3) * 8;
    // B staging: 2 thr/row (128 rows), each 32 halves (4 uint4)
    const int brow = tid >> 1;
    const int k2h  = (tid & 1) * 16;

    const __half* aptr = A  + (size_t)(row0 + arow) * KDIM + k2q * 2;
    const __half* bptr = WH + (size_t)(col0 + brow) * KDIM + k2h * 2;

    const int lane = tid & 31, warp = tid >> 5;
    const int g = lane >> 2, tig = lane & 3;
    const int wm = (warp >> 2) * 32, wn = (warp & 3) * 32;

    float acc[2][4][4];
#pragma unroll
    for (int mf = 0; mf < 2; mf++)
#pragma unroll
        for (int nf = 0; nf < 4; nf++)
#pragma unroll
            for (int i = 0; i < 4; i++) acc[mf][nf][i] = 0.f;

    uint4 pa[2], pb[4];
#pragma unroll
    for (int j = 0; j < 2; j++) pa[j] = *(const uint4*)(aptr + j * 8);
#pragma unroll
    for (int j = 0; j < 4; j++) pb[j] = *(const uint4*)(bptr + j * 8);

    for (int kt = 0; kt < NKT; kt++) {
#pragma unroll
        for (int j = 0; j < 2; j++) {
            As[k2q + j * 4 + 0][arow] = pa[j].x;
            As[k2q + j * 4 + 1][arow] = pa[j].y;
            As[k2q + j * 4 + 2][arow] = pa[j].z;
            As[k2q + j * 4 + 3][arow] = pa[j].w;
        }
#pragma unroll
        for (int j = 0; j < 4; j++) {
            Bs[k2h + j * 4 + 0][brow] = pb[j].x;
            Bs[k2h + j * 4 + 1][brow] = pb[j].y;
            Bs[k2h + j * 4 + 2][brow] = pb[j].z;
            Bs[k2h + j * 4 + 3][brow] = pb[j].w;
        }
        __syncthreads();

        if (kt + 1 < NKT) {
            aptr += 64; bptr += 64;
#pragma unroll
            for (int j = 0; j < 2; j++) pa[j] = *(const uint4*)(aptr + j * 8);
#pragma unroll
            for (int j = 0; j < 4; j++) pb[j] = *(const uint4*)(bptr + j * 8);
        }

#pragma unroll
        for (int ks = 0; ks < 4; ks++) {
            const int k8 = ks * 8;
            uint32_t af[2][4], bf[4][2];
#pragma unroll
            for (int mf = 0; mf < 2; mf++) {
                const int m = wm + mf * 16 + g;
                af[mf][0] = As[k8 + tig][m];
                af[mf][1] = As[k8 + tig][m + 8];
                af[mf][2] = As[k8 + tig + 4][m];
                af[mf][3] = As[k8 + tig + 4][m + 8];
            }
#pragma unroll
            for (int nf = 0; nf < 4; nf++) {
                const int n = wn + nf * 8 + g;
                bf[nf][0] = Bs[k8 + tig][n];
                bf[nf][1] = Bs[k8 + tig + 4][n];
            }
#pragma unroll
            for (int mf = 0; mf < 2; mf++)
#pragma unroll
                for (int nf = 0; nf < 4; nf++)
                    mma_f16(acc[mf][nf], af[mf], bf[nf]);
        }
        __syncthreads();
    }

    float2 bv[4];
#pragma unroll
    for (int nf = 0; nf < 4; nf++) {
        if (isE) bv[nf] = make_float2(0.f, 0.f);
        else     bv[nf] = *(const float2*)(bias + col0 + wn + nf * 8 + tig * 2);
    }
#pragma unroll
    for (int mf = 0; mf < 2; mf++) {
        const int r = row0 + wm + mf * 16 + g;
#pragma unroll
        for (int nf = 0; nf < 4; nf++) {
            const int c = col0 + wn + nf * 8 + tig * 2;
            float2 v0 = make_float2(acc[mf][nf][0] + bv[nf].x,
                                    acc[mf][nf][1] + bv[nf].y);
            float2 v1 = make_float2(acc[mf][nf][2] + bv[nf].x,
                                    acc[mf][nf][3] + bv[nf].y);
            *(float2*)(C + (size_t)r * NDIM + c)       = v0;
            *(float2*)(C + (size_t)(r + 8) * NDIM + c) = v1;
        }
    }
}

// ---------------------------------------------------------------------------
// Range broadcast add with u-split + streaming stores (R15, measured):
// ---------------------------------------------------------------------------
template <int US>
__global__ void __launch_bounds__(256)
bcast_r(const float* __restrict__ E, const float* __restrict__ D,
        float* __restrict__ out, int b0)
{
    const int t    = blockIdx.x & 255;
    const int rest = blockIdx.x >> 8;
    const int b    = b0 + rest / US;
    const int u0   = (rest % US) * (64 / US);
    const int v4   = threadIdx.x;

    const float4* E4 = (const float4*)E;
    const float4* D4 = (const float4*)D;
    float4*       O4 = (float4*)out;

    const float4 e = E4[(size_t)(b * 256 + t) * 256 + v4];
    const size_t base = ((size_t)(b * 256 + t) * 64) * 256 + v4;
    const float4* Dp  = D4 + (size_t)(b * 64) * 256 + v4;

    for (int u = u0; u < u0 + 64 / US; u += 4) {
        float4 d0 = __ldg(Dp + (size_t)(u + 0) * 256);
        float4 d1 = __ldg(Dp + (size_t)(u + 1) * 256);
        float4 d2 = __ldg(Dp + (size_t)(u + 2) * 256);
        float4 d3 = __ldg(Dp + (size_t)(u + 3) * 256);

        const size_t o = base + (size_t)u * 256;
        __stcs(O4 + o,
               make_float4(e.x + d0.x, e.y + d0.y, e.z + d0.z, e.w + d0.w));
        __stcs(O4 + o + 256,
               make_float4(e.x + d1.x, e.y + d1.y, e.z + d1.z, e.w + d1.w));
        __stcs(O4 + o + 2 * 256,
               make_float4(e.x + d2.x, e.y + d2.y, e.z + d2.z, e.w + d2.w));
        __stcs(O4 + o + 3 * 256,
               make_float4(e.x + d3.x, e.y + d3.y, e.z + d3.z, e.w + d3.w));
    }
}

// ---------------------------------------------------------------------------
// Schedule:
//   stream0: cvtA -> gemmA (D + E b0,b1; 128 CTAs) -> evA
//            -> cvtB -> gemmB (E b2..7; 192 CTAs) -> evB
//   side:    wait evA -> bcastA (b0,b1; u-split x2); wait evB -> bcastB; join.
// ---------------------------------------------------------------------------
static cudaStream_t s_bc = nullptr;
static cudaEvent_t  s_evA, s_evB, s_join;
static int s_state = 0;

extern "C" void kernel_launch(void* const* d_in, const int* in_sizes, int n_in,
                              void* d_out, int out_size) {
    const float* enc  = (const float*)d_in[0];  // (8,256,512)
    const float* dec  = (const float*)d_in[1];  // (8,64,512)
    const float* W    = (const float*)d_in[2];  // (1024,512)
    const float* bias = (const float*)d_in[3];  // (1024,)
    float* out = (float*)d_out;                 // (8,256,64,1024)

    float *E, *D;
    cudaGetSymbolAddress((void**)&E, g_E);
    cudaGetSymbolAddress((void**)&D, g_D);

    if (s_state == 0) {
        s_state = 1;
        if (cudaStreamCreateWithFlags(&s_bc, cudaStreamNonBlocking) != cudaSuccess)
            s_state = -1;
        if (s_state == 1 &&
            (cudaEventCreateWithFlags(&s_evA, cudaEventDisableTiming) != cudaSuccess ||
             cudaEventCreateWithFlags(&s_evB, cudaEventDisableTiming) != cudaSuccess ||
             cudaEventCreateWithFlags(&s_join, cudaEventDisableTiming) != cudaSuccess))
            s_state = -1;
    }

    const int cvtA_blocks = (int)((ENC01_N + DEC_N + W_N) / 8 / 256);  // 512
    const int cvtB_blocks = (int)((ENC_N - ENC01_N) / 8 / 256);        // 384

    if (s_state == 1) {
        cvtA_f16<<<cvtA_blocks, 256>>>(enc, dec, W);
        gemm_f16<<<dim3(8, 16), 256>>>(bias, E, D, 0);   // D + E(b0,b1)
        cudaEventRecord(s_evA, 0);
        cvtB_f16<<<cvtB_blocks, 256>>>(enc);
        gemm_f16<<<dim3(8, 24), 256>>>(bias, E, D, 16);  // E(b2..b7)
        cudaEventRecord(s_evB, 0);

        cudaStreamWaitEvent(s_bc, s_evA, 0);
        bcast_r<2><<<1024, 256, 0, s_bc>>>(E, D, out, 0);   // b0,b1
        cudaStreamWaitEvent(s_bc, s_evB, 0);
        bcast_r<1><<<1536, 256, 0, s_bc>>>(E, D, out, 2);   // b2..b7

        cudaEventRecord(s_join, s_bc);
        cudaStreamWaitEvent(0, s_join, 0);
    } else {
        cvtA_f16<<<cvtA_blocks, 256>>>(enc, dec, W);
        cvtB_f16<<<cvtB_blocks, 256>>>(enc);
        gemm_f16<<<dim3(8, 16), 256>>>(bias, E, D, 0);
        gemm_f16<<<dim3(8, 24), 256>>>(bias, E, D, 16);
        bcast_r<2><<<1024, 256>>>(E, D, out, 0);
        bcast_r<1><<<1536, 256>>>(E, D, out, 2);
    }
}